// round 5
// baseline (speedup 1.0000x reference)
#include <cuda_runtime.h>

// Problem constants
#define Bn 16
#define Jn 16
#define Cn 64
#define Hn 256
#define Wn 256
#define HWn (Hn * Wn)          // 65536
#define SPLIT 4
#define CHUNK (HWn / SPLIT)    // 16384 floats per split-block
#define NPART (Bn * Jn * SPLIT)
#define BLKS_PER_B (Jn * SPLIT)   // 64 blocks feed each batch
#define QPT 16                    // float4s (quads) per thread: CHUNK/4/256

#define NEG_INF (-3.4028235e38f)

// Scratch (device globals: allocation-free). g_count starts zeroed; each
// finalizer resets its slot so graph replays are deterministic.
__device__ float g_pval[NPART];
__device__ int   g_pidx[NPART];
__device__ int   g_count[Bn];

// ---------------------------------------------------------------------------
// Fused kernel: split-K argmax (max-then-find) + last-block-per-batch finalize
// grid = B*J*SPLIT = 1024 blocks, 256 threads.
// ---------------------------------------------------------------------------
__global__ __launch_bounds__(256) void fused_labelloss_kernel(
    const float* __restrict__ heatmap,
    const float* __restrict__ pred,
    const float* __restrict__ gt,
    float* __restrict__ out)
{
    const int blk = blockIdx.x;
    const int bj  = blk / SPLIT;         // 0..255  (= b*Jn + j)
    const int s   = blk % SPLIT;
    const int b   = bj / Jn;
    const int t   = threadIdx.x;
    const int wid = t >> 5, lid = t & 31;

    const float4* __restrict__ src = reinterpret_cast<const float4*>(
        heatmap + (size_t)bj * HWn + (size_t)s * CHUNK);

    // -------- Pass 1: pure max (no index tracking, no predicate chains) -----
    float qm[QPT];      // per-quad maxes, register resident
    float m = NEG_INF;

    #pragma unroll
    for (int it = 0; it < QPT; ++it) {
        const float4 v = __ldg(&src[t + it * 256]);
        qm[it] = fmaxf(fmaxf(v.x, v.y), fmaxf(v.z, v.w));
        m = fmaxf(m, qm[it]);
    }

    // warp max (xor butterfly: all lanes end with warp max)
    #pragma unroll
    for (int off = 16; off > 0; off >>= 1)
        m = fmaxf(m, __shfl_xor_sync(0xffffffff, m, off));

    __shared__ float swm[8];
    __shared__ float s_bmax;
    __shared__ int   s_bidx;
    __shared__ int   s_last;

    if (lid == 0) swm[wid] = m;
    if (t == 0)   s_bidx = 0x7fffffff;
    __syncthreads();

    if (t < 32) {
        float mm = (t < 8) ? swm[t] : NEG_INF;
        #pragma unroll
        for (int off = 4; off > 0; off >>= 1)
            mm = fmaxf(mm, __shfl_xor_sync(0xffffffff, mm, off));
        if (t == 0) s_bmax = mm;
    }
    __syncthreads();

    const float bmax = s_bmax;

    // -------- Pass 2: find first (lowest flat index) occurrence of bmax -----
    // Register compares only; the drill-down reload is ~1 thread per block.
    #pragma unroll
    for (int it = 0; it < QPT; ++it) {
        if (qm[it] == bmax) {
            const int p = t + it * 256;
            const float4 v = __ldg(&src[p]);
            const int base = s * CHUNK + p * 4;
            if (v.x == bmax) atomicMin(&s_bidx, base + 0);
            if (v.y == bmax) atomicMin(&s_bidx, base + 1);
            if (v.z == bmax) atomicMin(&s_bidx, base + 2);
            if (v.w == bmax) atomicMin(&s_bidx, base + 3);
        }
    }
    __syncthreads();

    // -------- Publish partial; 64th arriver per batch finalizes -------------
    if (t == 0) {
        g_pval[bj * SPLIT + s] = bmax;
        g_pidx[bj * SPLIT + s] = s_bidx;
        __threadfence();
        const int prev = atomicAdd(&g_count[b], 1);
        s_last = (prev == BLKS_PER_B - 1) ? 1 : 0;
    }
    __syncthreads();

    if (!s_last) return;

    // ------------------- Finalize batch b: gather + MSE ---------------------
    __shared__ int s_idx[Jn];

    if (t < Jn) {
        const int base = (b * Jn + t) * SPLIT;
        float bv = NEG_INF;
        int   bi = 0x7fffffff;
        #pragma unroll
        for (int k = 0; k < SPLIT; ++k) {
            const float v = __ldcg(&g_pval[base + k]);
            const int   i = __ldcg(&g_pidx[base + k]);
            if (v > bv || (v == bv && i < bi)) { bv = v; bi = i; }
        }
        s_idx[t] = bi;
    }
    __syncthreads();

    // J*C = 1024 gathered elements, 256 threads -> 4 each
    float acc = 0.0f;
    #pragma unroll
    for (int it = 0; it < (Jn * Cn) / 256; ++it) {
        const int e = t + it * 256;
        const int j = e >> 6;        // /64
        const int c = e & 63;        // %64
        const int idx = s_idx[j];
        const float p = __ldg(&pred[((size_t)b * Cn + c) * HWn + idx]);
        const float g = __ldg(&gt[((size_t)b * Jn + j) * Cn + c]);
        const float d = p - g;
        acc += d * d;
    }

    #pragma unroll
    for (int off = 16; off > 0; off >>= 1)
        acc += __shfl_down_sync(0xffffffff, acc, off);

    __shared__ float ss[8];
    if (lid == 0) ss[wid] = acc;
    __syncthreads();
    if (t < 32) {
        acc = (lid < 8) ? ss[lid] : 0.0f;
        #pragma unroll
        for (int off = 4; off > 0; off >>= 1)
            acc += __shfl_down_sync(0xffffffff, acc, off);
        if (lid == 0) {
            out[b] = acc * (1.0f / (Jn * Cn));
            g_count[b] = 0;   // reset for next graph replay
        }
    }
}

extern "C" void kernel_launch(void* const* d_in, const int* in_sizes, int n_in,
                              void* d_out, int out_size)
{
    const float* pred    = (const float*)d_in[0];   // [B,C,H,W]
    const float* gt      = (const float*)d_in[1];   // [B,J,C]
    const float* heatmap = (const float*)d_in[2];   // [B,J,H,W]
    float* out = (float*)d_out;                     // [B]

    fused_labelloss_kernel<<<NPART, 256>>>(heatmap, pred, gt, out);
}